// round 1
// baseline (speedup 1.0000x reference)
#include <cuda_runtime.h>
#include <math_constants.h>

#define HH 1024
#define WW 1024
#define NB 16
#define NPIX (NB * HH * WW)

// Ping-pong scratch (allocation-free: device globals)
__device__ float g_bufA[NPIX];
__device__ float g_bufB[NPIX];

#define TILE   32   // output tile (maxpool outputs) per block
#define CONV_H 34   // conv points rows needed (tile + 1 halo each side)
#define CONV_W 36   // conv cols padded to multiple of 4 (34 used)
#define IN_H   40   // input rows needed: CONV_H + 6
#define IN_W   42   // input cols needed: CONV_W + 6

// Fused 7x7 conv (zero pad 3) + 3x3 maxpool (stride 1, -inf pad)
__global__ __launch_bounds__(256) void conv_max_kernel(const float* __restrict__ src,
                                                       float* __restrict__ dst)
{
    __shared__ float sIn[IN_H][IN_W];
    __shared__ float sConv[CONV_H][CONV_W];

    const int bx  = blockIdx.x;
    const int by  = blockIdx.y;
    const int b   = blockIdx.z;
    const int tid = threadIdx.x;
    const long long base = (long long)b * HH * WW;

    const int gy0 = by * TILE - 4;  // input tile origin (conv halo 1 + radius 3)
    const int gx0 = bx * TILE - 4;

    // ---- load input tile (zero padded) ----
    #pragma unroll
    for (int i = tid; i < IN_H * IN_W; i += 256) {
        int iy = i / IN_W;
        int ix = i - iy * IN_W;
        int gy = gy0 + iy;
        int gx = gx0 + ix;
        float v = 0.0f;
        if (gy >= 0 && gy < HH && gx >= 0 && gx < WW)
            v = src[base + (long long)gy * WW + gx];
        sIn[iy][ix] = v;
    }
    __syncthreads();

    // ---- conv at 34x34 points (register-blocked strips of 4 in x) ----
    const float c1 = 1.0f / 24.0f;
    const float c3 = 3.0f / 24.0f;
    const float c7 = 7.0f / 24.0f;

    for (int task = tid; task < CONV_H * 9; task += 256) {
        int cy = task / 9;
        int sx = (task - cy * 9) * 4;   // 0..32

        float acc0 = 0.f, acc1 = 0.f, acc2 = 0.f, acc3 = 0.f;
        float r[10];

        #define LOADR(KY) { \
            _Pragma("unroll") \
            for (int j = 0; j < 10; ++j) r[j] = sIn[cy + (KY)][sx + j]; }

        #define TAP(KX, WV) { \
            acc0 = fmaf((WV), r[(KX)    ], acc0); \
            acc1 = fmaf((WV), r[(KX) + 1], acc1); \
            acc2 = fmaf((WV), r[(KX) + 2], acc2); \
            acc3 = fmaf((WV), r[(KX) + 3], acc3); }

        // row patterns of _KERNEL/24 (nonzero taps only):
        // A: [0,0,1,1,1,0,0]
        // B: [0,1,3,3,3,1,0]
        // C: [1,3,0,-7,0,3,0]
        // D: [1,3,-7,-24,-7,3,1]
        #define ROW_A TAP(2, c1)  TAP(3, c1)  TAP(4, c1)
        #define ROW_B TAP(1, c1)  TAP(2, c3)  TAP(3, c3)  TAP(4, c3)  TAP(5, c1)
        #define ROW_C TAP(0, c1)  TAP(1, c3)  TAP(3, -c7) TAP(5, c3)
        #define ROW_D TAP(0, c1)  TAP(1, c3)  TAP(2, -c7) TAP(3, -1.0f) \
                      TAP(4, -c7) TAP(5, c3)  TAP(6, c1)

        LOADR(0) ROW_A
        LOADR(1) ROW_B
        LOADR(2) ROW_C
        LOADR(3) ROW_D
        LOADR(4) ROW_C
        LOADR(5) ROW_B
        LOADR(6) ROW_A

        #undef LOADR
        #undef TAP
        #undef ROW_A
        #undef ROW_B
        #undef ROW_C
        #undef ROW_D

        const int gy = by * TILE + cy - 1;
        const bool rowok = (gy >= 0) && (gy < HH);
        const int gxb = bx * TILE + sx - 1;

        sConv[cy][sx + 0] = (rowok && (gxb + 0) >= 0 && (gxb + 0) < WW) ? acc0 : -CUDART_INF_F;
        sConv[cy][sx + 1] = (rowok && (gxb + 1) >= 0 && (gxb + 1) < WW) ? acc1 : -CUDART_INF_F;
        sConv[cy][sx + 2] = (rowok && (gxb + 2) >= 0 && (gxb + 2) < WW) ? acc2 : -CUDART_INF_F;
        sConv[cy][sx + 3] = (rowok && (gxb + 3) >= 0 && (gxb + 3) < WW) ? acc3 : -CUDART_INF_F;
    }
    __syncthreads();

    // ---- 3x3 maxpool over conv points, write 32x32 outputs ----
    const int ox  = tid & 31;
    const int oy0 = tid >> 5;   // 0..7
    #pragma unroll
    for (int i = 0; i < 4; ++i) {
        int oy = oy0 + 8 * i;
        float m = sConv[oy][ox];
        m = fmaxf(m, sConv[oy    ][ox + 1]);
        m = fmaxf(m, sConv[oy    ][ox + 2]);
        m = fmaxf(m, sConv[oy + 1][ox    ]);
        m = fmaxf(m, sConv[oy + 1][ox + 1]);
        m = fmaxf(m, sConv[oy + 1][ox + 2]);
        m = fmaxf(m, sConv[oy + 2][ox    ]);
        m = fmaxf(m, sConv[oy + 2][ox + 1]);
        m = fmaxf(m, sConv[oy + 2][ox + 2]);
        dst[base + (long long)(by * TILE + oy) * WW + (bx * TILE + ox)] = m;
    }
}

// Fused: threshold(>0.5) -> 3x3 avgpool(/9, zero pad) -> (>0.8) -> y ; mask == y
// avg/9 > 0.8  <=>  count(ones in 3x3) >= 8
__global__ __launch_bounds__(256) void finalize_kernel(const float* __restrict__ src,
                                                       float* __restrict__ out,
                                                       int dup)
{
    int idx = blockIdx.x * 256 + threadIdx.x;
    if (idx >= NPIX) return;

    int x = idx & (WW - 1);
    int y = (idx >> 10) & (HH - 1);
    long long bbase = (long long)idx - x - (long long)y * WW;

    int cnt = 0;
    #pragma unroll
    for (int dy = -1; dy <= 1; ++dy) {
        int ny = y + dy;
        if (ny < 0 || ny >= HH) continue;
        #pragma unroll
        for (int dx = -1; dx <= 1; ++dx) {
            int nx = x + dx;
            if (nx < 0 || nx >= WW) continue;
            cnt += (src[bbase + (long long)ny * WW + nx] > 0.5f) ? 1 : 0;
        }
    }
    float v = (cnt >= 8) ? 1.0f : 0.0f;
    out[idx] = v;
    if (dup) out[(long long)NPIX + idx] = v;
}

extern "C" void kernel_launch(void* const* d_in, const int* in_sizes, int n_in,
                              void* d_out, int out_size)
{
    const float* x = (const float*)d_in[0];
    float* out = (float*)d_out;

    float *A, *B;
    cudaGetSymbolAddress((void**)&A, g_bufA);
    cudaGetSymbolAddress((void**)&B, g_bufB);

    dim3 grid(WW / TILE, HH / TILE, NB);

    conv_max_kernel<<<grid, 256>>>(x, A);
    conv_max_kernel<<<grid, 256>>>(A, B);
    conv_max_kernel<<<grid, 256>>>(B, A);
    conv_max_kernel<<<grid, 256>>>(A, B);

    int dup = (out_size >= 2 * NPIX) ? 1 : 0;
    finalize_kernel<<<(NPIX + 255) / 256, 256>>>(B, out, dup);
}

// round 3
// speedup vs baseline: 2.1101x; 2.1101x over previous
#include <cuda_runtime.h>
#include <math_constants.h>

#define HH 1024
#define WW 1024
#define NB 16
#define NPIX (NB * HH * WW)
#define TH 64            // output rows per block (row chunk)
#define NOUT 11          // outer loop iters: 11*7 = 77 steps >= TH+10

__device__ __align__(256) float g_bufA[NPIX];
__device__ __align__(256) float g_bufB[NPIX];

#define C1 (1.0f / 24.0f)
#define C3 (3.0f / 24.0f)
#define C7 (7.0f / 24.0f)
#define NEGINF (-CUDART_INF_F)

struct Ctx {
    const float* sp;   // src, batch-offset
    float* dp;         // dst, batch-offset (stage output or final out base)
    int lane, c0, ecc, Y0, CFIRST, dup;
    bool writeok;
    bool cv[4];        // conv col within image
};

struct St {
    float a[7][4];     // pending conv accumulators (ring), 4 cols/lane
    float4 ownN, extN; // prefetched next input row
    float cp[4], pm[4];  // conv row history for vertical max
    int bp1[4], bp2[4];  // bit history for fused avgpool (FINAL)
};

__device__ __forceinline__ float4 ld4(const float* __restrict__ p, int r, int cc) {
    if ((unsigned)r < (unsigned)HH && (unsigned)cc < (unsigned)WW)
        return *reinterpret_cast<const float4*>(p + (size_t)r * WW + cc);
    return make_float4(0.f, 0.f, 0.f, 0.f);
}

template<int U, bool FIN>
__device__ __forceinline__ void step(St& s, const Ctx& c, int r)
{
    const unsigned FULL = 0xffffffffu;
    float4 own = s.ownN;
    float4 ext = s.extN;
    // prefetch next row
    s.ownN = ld4(c.sp, r + 1, c.c0);
    s.extN = (c.lane == 0 || c.lane == 31) ? ld4(c.sp, r + 1, c.ecc)
                                           : make_float4(0.f, 0.f, 0.f, 0.f);

    // build 10-wide input window w[0..9] = input cols c0-3 .. c0+6
    float w0 = __shfl_up_sync(FULL, own.y, 1);
    float w1 = __shfl_up_sync(FULL, own.z, 1);
    float w2 = __shfl_up_sync(FULL, own.w, 1);
    if (c.lane == 0) { w0 = ext.y; w1 = ext.z; w2 = ext.w; }
    float w7 = __shfl_down_sync(FULL, own.x, 1);
    float w8 = __shfl_down_sync(FULL, own.y, 1);
    float w9 = __shfl_down_sync(FULL, own.z, 1);
    if (c.lane == 31) { w7 = ext.x; w8 = ext.y; w9 = ext.z; }

    float w[10] = { w0, w1, w2, own.x, own.y, own.z, own.w, w7, w8, w9 };

    // horizontal filters for the 4 distinct kernel row patterns, accumulate
    // into the 7-deep ring (compile-time indices via template U)
    #pragma unroll
    for (int k = 0; k < 4; ++k) {
        float t  = w[k + 2] + w[k + 3] + w[k + 4];
        float uu = w[k + 1] + w[k + 5];
        float vv = w[k + 0] + w[k + 6];
        float x2 = w[k + 2] + w[k + 4];
        float hA = C1 * t;                                             // [0,0,1,1,1,0,0]/24
        float hB = fmaf(C3, t, C1 * uu);                               // [0,1,3,3,3,1,0]/24
        float hC = fmaf(C3, uu, fmaf(-C7, w[k + 3], C1 * w[k + 0]));   // [1,3,0,-7,0,3,0]/24
        float hD = fmaf(C3, uu, fmaf(-C7, x2, C1 * vv)) - w[k + 3];    // [1,3,-7,-24,-7,3,1]/24
        s.a[(U + 0) % 7][k] += hA;
        s.a[(U + 1) % 7][k] += hB;
        s.a[(U + 2) % 7][k] += hC;
        s.a[(U + 3) % 7][k] += hD;
        s.a[(U + 4) % 7][k] += hC;
        s.a[(U + 5) % 7][k] += hB;
        s.a[(U + 6) % 7][k] += hA;
    }

    // ---- read + RESET the completed ring slot UNCONDITIONALLY ----
    // (slots must be zeroed every 7 steps even during warm-up, otherwise
    //  partial sums for never-read conv rows pollute later conv rows)
    const int cr = r - 3;              // conv row completed this step
    float raw[4];
    #pragma unroll
    for (int k = 0; k < 4; ++k) { raw[k] = s.a[U % 7][k]; s.a[U % 7][k] = 0.f; }

    if (cr >= c.CFIRST) {
        const bool rv = (unsigned)cr < (unsigned)HH;
        float cur[4], vm[4];
        #pragma unroll
        for (int k = 0; k < 4; ++k) {
            cur[k] = (rv && c.cv[k]) ? raw[k] : NEGINF;
            vm[k]  = fmaxf(s.pm[k], cur[k]);          // vmax for row cr-1
            s.pm[k] = fmaxf(cur[k], s.cp[k]);
            s.cp[k] = cur[k];
        }
        float vmL = __shfl_up_sync(FULL, vm[3], 1);
        float vmR = __shfl_down_sync(FULL, vm[0], 1);
        float m0 = fmaxf(vmL,   fmaxf(vm[0], vm[1]));
        float m1 = fmaxf(vm[0], fmaxf(vm[1], vm[2]));
        float m2 = fmaxf(vm[1], fmaxf(vm[2], vm[3]));
        float m3 = fmaxf(vm[2], fmaxf(vm[3], vmR));
        const int v = cr - 1;          // maxpool output row

        if (!FIN) {
            if (c.writeok && v >= c.Y0 && v < c.Y0 + TH && v < HH)
                *reinterpret_cast<float4*>(c.dp + (size_t)v * WW + c.c0)
                    = make_float4(m0, m1, m2, m3);
        } else {
            // fused: threshold -> 3x3 count (>=8 <=> avg/9 > 0.8) -> threshold
            // binary value exists only for in-image rows AND columns (zero pad)
            const bool bv = (unsigned)v < (unsigned)HH;
            int b0 = (bv && c.cv[0] && m0 > 0.5f) ? 1 : 0;
            int b1 = (bv && c.cv[1] && m1 > 0.5f) ? 1 : 0;
            int b2 = (bv && c.cv[2] && m2 > 0.5f) ? 1 : 0;
            int b3 = (bv && c.cv[3] && m3 > 0.5f) ? 1 : 0;
            int s0 = s.bp2[0] + s.bp1[0] + b0;
            int s1 = s.bp2[1] + s.bp1[1] + b1;
            int s2 = s.bp2[2] + s.bp1[2] + b2;
            int s3 = s.bp2[3] + s.bp1[3] + b3;
            s.bp2[0] = s.bp1[0]; s.bp2[1] = s.bp1[1];
            s.bp2[2] = s.bp1[2]; s.bp2[3] = s.bp1[3];
            s.bp1[0] = b0; s.bp1[1] = b1; s.bp1[2] = b2; s.bp1[3] = b3;
            int sL = __shfl_up_sync(FULL, s3, 1);
            int sR = __shfl_down_sync(FULL, s0, 1);
            int n0 = sL + s0 + s1;
            int n1 = s0 + s1 + s2;
            int n2 = s1 + s2 + s3;
            int n3 = s2 + s3 + sR;
            const int wr = v - 1;      // final output row
            if (c.writeok && wr >= c.Y0 && wr < c.Y0 + TH && (unsigned)wr < (unsigned)HH) {
                float4 o = make_float4(n0 >= 8 ? 1.f : 0.f, n1 >= 8 ? 1.f : 0.f,
                                       n2 >= 8 ? 1.f : 0.f, n3 >= 8 ? 1.f : 0.f);
                float* op = c.dp + (size_t)wr * WW + c.c0;
                *reinterpret_cast<float4*>(op) = o;
                if (c.dup)
                    *reinterpret_cast<float4*>(op + NPIX) = o;   // mask == y
            }
        }
    }
}

template<bool FIN>
__global__ void __launch_bounds__(32) sweep_kernel(const float* __restrict__ src,
                                                   float* __restrict__ dst,
                                                   int dup)
{
    Ctx c;
    c.lane = threadIdx.x;
    const int sx = blockIdx.x;              // 0..8 column strips
    c.Y0 = blockIdx.y * TH;
    const int b = blockIdx.z;
    const int X0 = 120 * sx - 4;            // strip conv-col origin
    c.c0  = X0 + 4 * c.lane;                // this lane's 4 conv cols (4-aligned)
    c.ecc = (c.lane == 0) ? (c.c0 - 4) : (c.c0 + 4);
    c.sp  = src + (size_t)b * HH * WW;
    c.dp  = dst + (size_t)b * HH * WW;
    c.dup = dup;
    c.writeok = (c.lane >= 1) && (c.lane <= 30) && (c.c0 < WW);   // interior 120 cols
    #pragma unroll
    for (int k = 0; k < 4; ++k) c.cv[k] = (unsigned)(c.c0 + k) < (unsigned)WW;
    c.CFIRST = FIN ? (c.Y0 - 2) : (c.Y0 - 1);
    const int rs = FIN ? (c.Y0 - 5) : (c.Y0 - 4);

    St s;
    #pragma unroll
    for (int i = 0; i < 7; ++i) {
        #pragma unroll
        for (int k = 0; k < 4; ++k) s.a[i][k] = 0.f;
    }
    #pragma unroll
    for (int k = 0; k < 4; ++k) {
        s.cp[k] = NEGINF; s.pm[k] = NEGINF; s.bp1[k] = 0; s.bp2[k] = 0;
    }
    s.ownN = ld4(c.sp, rs, c.c0);
    s.extN = (c.lane == 0 || c.lane == 31) ? ld4(c.sp, rs, c.ecc)
                                           : make_float4(0.f, 0.f, 0.f, 0.f);

    int r = rs;
    for (int it = 0; it < NOUT; ++it) {
        step<0, FIN>(s, c, r + 0);
        step<1, FIN>(s, c, r + 1);
        step<2, FIN>(s, c, r + 2);
        step<3, FIN>(s, c, r + 3);
        step<4, FIN>(s, c, r + 4);
        step<5, FIN>(s, c, r + 5);
        step<6, FIN>(s, c, r + 6);
        r += 7;
    }
}

extern "C" void kernel_launch(void* const* d_in, const int* in_sizes, int n_in,
                              void* d_out, int out_size)
{
    const float* x = (const float*)d_in[0];
    float* out = (float*)d_out;

    float *A, *B;
    cudaGetSymbolAddress((void**)&A, g_bufA);
    cudaGetSymbolAddress((void**)&B, g_bufB);

    dim3 grid(9, HH / TH, NB);   // (x-strips, row chunks, batch)
    dim3 block(32);

    int dup = (out_size >= 2 * NPIX) ? 1 : 0;

    sweep_kernel<false><<<grid, block>>>(x, A, 0);
    sweep_kernel<false><<<grid, block>>>(A, B, 0);
    sweep_kernel<false><<<grid, block>>>(B, A, 0);
    sweep_kernel<true ><<<grid, block>>>(A, out, dup);
}

// round 4
// speedup vs baseline: 2.1332x; 1.0109x over previous
#include <cuda_runtime.h>
#include <math_constants.h>

#define HH 1024
#define WW 1024
#define NB 16
#define NPIX (NB * HH * WW)
#define TH 32            // output rows per block (row chunk)
#define NOUT 6           // 6*7 = 42 steps >= TH+10

__device__ __align__(256) float g_bufA[NPIX];
__device__ __align__(256) float g_bufB[NPIX];

#define C1 (1.0f / 24.0f)
#define C3 (3.0f / 24.0f)
#define C7 (7.0f / 24.0f)
#define NEGINF (-CUDART_INF_F)

typedef unsigned long long u64;

// ---- packed f32x2 helpers (sm_103a FFMA2/FADD2 — PTX-only) ----
#define PK2(d, lo, hi)  asm("mov.b64 %0, {%1, %2};" : "=l"(d) : "f"(lo), "f"(hi))
#define UPK2(lo, hi, s) asm("mov.b64 {%0, %1}, %2;" : "=f"(lo), "=f"(hi) : "l"(s))
#define ADD2(d, a, b)   asm("add.rn.f32x2 %0, %1, %2;" : "=l"(d) : "l"(a), "l"(b))
#define ACC2(d, b)      asm("add.rn.f32x2 %0, %0, %1;" : "+l"(d) : "l"(b))
#define MUL2(d, a, b)   asm("mul.rn.f32x2 %0, %1, %2;" : "=l"(d) : "l"(a), "l"(b))
#define FMA2(d, a, b, c) asm("fma.rn.f32x2 %0, %1, %2, %3;" : "=l"(d) : "l"(a), "l"(b), "l"(c))

struct Ctx {
    const float* sp;
    float* dp;
    int lane, c0, ecc, Y0, CFIRST, dup;
    bool writeok;
    bool cv[4];
    u64 kC1, kC3, kM7, kM1;   // packed (c,c) constants
};

struct St {
    u64 a[7][2];       // pending conv accumulators (ring), 2 f32x2 pairs/lane
    float4 ownN, extN;
    float cp[4], pm[4];
    int bp1[4], bp2[4];
};

__device__ __forceinline__ float4 ld4(const float* __restrict__ p, int r, int cc) {
    if ((unsigned)r < (unsigned)HH && (unsigned)cc < (unsigned)WW)
        return *reinterpret_cast<const float4*>(p + (size_t)r * WW + cc);
    return make_float4(0.f, 0.f, 0.f, 0.f);
}

template<int U, bool FIN>
__device__ __forceinline__ void step(St& s, const Ctx& c, int r)
{
    const unsigned FULL = 0xffffffffu;
    float4 own = s.ownN;
    float4 ext = s.extN;
    s.ownN = ld4(c.sp, r + 1, c.c0);
    s.extN = (c.lane == 0 || c.lane == 31) ? ld4(c.sp, r + 1, c.ecc)
                                           : make_float4(0.f, 0.f, 0.f, 0.f);

    // 10-wide window w[0..9] = input cols c0-3 .. c0+6
    float w0 = __shfl_up_sync(FULL, own.y, 1);
    float w1 = __shfl_up_sync(FULL, own.z, 1);
    float w2 = __shfl_up_sync(FULL, own.w, 1);
    if (c.lane == 0) { w0 = ext.y; w1 = ext.z; w2 = ext.w; }
    float w7 = __shfl_down_sync(FULL, own.x, 1);
    float w8 = __shfl_down_sync(FULL, own.y, 1);
    float w9 = __shfl_down_sync(FULL, own.z, 1);
    if (c.lane == 31) { w7 = ext.x; w8 = ext.y; w9 = ext.z; }

    float w[10] = { w0, w1, w2, own.x, own.y, own.z, own.w, w7, w8, w9 };

    // adjacent-pair packs P[j] = (w[j], w[j+1])
    u64 P[9];
    #pragma unroll
    for (int j = 0; j < 9; ++j) PK2(P[j], w[j], w[j + 1]);

    // two f32x2 pairs: p=0 -> cols {0,1}, p=1 -> cols {2,3}
    #pragma unroll
    for (int p = 0; p < 2; ++p) {
        const int o = 2 * p;
        u64 t1, Pt, Puu, Pvv, Px2;
        ADD2(t1, P[2 + o], P[3 + o]);
        ADD2(Pt, t1, P[4 + o]);
        ADD2(Puu, P[1 + o], P[5 + o]);
        ADD2(Pvv, P[0 + o], P[6 + o]);
        ADD2(Px2, P[2 + o], P[4 + o]);

        u64 hA, hB, hC, hD, m1, m2, m3, i1, i2, i3;
        MUL2(hA, c.kC1, Pt);                         // [0,0,1,1,1,0,0]/24
        MUL2(m1, c.kC1, Puu);
        FMA2(hB, c.kC3, Pt, m1);                     // [0,1,3,3,3,1,0]/24
        MUL2(m2, c.kC1, P[0 + o]);
        FMA2(i1, c.kM7, P[3 + o], m2);
        FMA2(hC, c.kC3, Puu, i1);                    // [1,3,0,-7,0,3,0]/24
        MUL2(m3, c.kC1, Pvv);
        FMA2(i2, c.kM7, Px2, m3);
        FMA2(i3, c.kC3, Puu, i2);
        FMA2(hD, c.kM1, P[3 + o], i3);               // [1,3,-7,-24,-7,3,1]/24

        ACC2(s.a[(U + 0) % 7][p], hA);
        ACC2(s.a[(U + 1) % 7][p], hB);
        ACC2(s.a[(U + 2) % 7][p], hC);
        ACC2(s.a[(U + 3) % 7][p], hD);
        ACC2(s.a[(U + 4) % 7][p], hC);
        ACC2(s.a[(U + 5) % 7][p], hB);
        ACC2(s.a[(U + 6) % 7][p], hA);
    }

    // read + RESET completed ring slot unconditionally
    const int cr = r - 3;
    float raw[4];
    UPK2(raw[0], raw[1], s.a[U % 7][0]);
    UPK2(raw[2], raw[3], s.a[U % 7][1]);
    s.a[U % 7][0] = 0ull;
    s.a[U % 7][1] = 0ull;

    if (cr >= c.CFIRST) {
        const bool rv = (unsigned)cr < (unsigned)HH;
        float cur[4], vm[4];
        #pragma unroll
        for (int k = 0; k < 4; ++k) {
            cur[k] = (rv && c.cv[k]) ? raw[k] : NEGINF;
            vm[k]  = fmaxf(s.pm[k], cur[k]);          // vmax for row cr-1
            s.pm[k] = fmaxf(cur[k], s.cp[k]);
            s.cp[k] = cur[k];
        }
        float vmL = __shfl_up_sync(FULL, vm[3], 1);
        float vmR = __shfl_down_sync(FULL, vm[0], 1);
        float m0 = fmaxf(vmL,   fmaxf(vm[0], vm[1]));
        float m1 = fmaxf(vm[0], fmaxf(vm[1], vm[2]));
        float m2 = fmaxf(vm[1], fmaxf(vm[2], vm[3]));
        float m3 = fmaxf(vm[2], fmaxf(vm[3], vmR));
        const int v = cr - 1;

        if (!FIN) {
            if (c.writeok && v >= c.Y0 && v < c.Y0 + TH && v < HH)
                *reinterpret_cast<float4*>(c.dp + (size_t)v * WW + c.c0)
                    = make_float4(m0, m1, m2, m3);
        } else {
            // threshold -> 3x3 count (>=8 <=> avg/9 > 0.8) -> threshold
            const bool bv = (unsigned)v < (unsigned)HH;
            int b0 = (bv && c.cv[0] && m0 > 0.5f) ? 1 : 0;
            int b1 = (bv && c.cv[1] && m1 > 0.5f) ? 1 : 0;
            int b2 = (bv && c.cv[2] && m2 > 0.5f) ? 1 : 0;
            int b3 = (bv && c.cv[3] && m3 > 0.5f) ? 1 : 0;
            int s0 = s.bp2[0] + s.bp1[0] + b0;
            int s1 = s.bp2[1] + s.bp1[1] + b1;
            int s2 = s.bp2[2] + s.bp1[2] + b2;
            int s3 = s.bp2[3] + s.bp1[3] + b3;
            s.bp2[0] = s.bp1[0]; s.bp2[1] = s.bp1[1];
            s.bp2[2] = s.bp1[2]; s.bp2[3] = s.bp1[3];
            s.bp1[0] = b0; s.bp1[1] = b1; s.bp1[2] = b2; s.bp1[3] = b3;
            int sL = __shfl_up_sync(FULL, s3, 1);
            int sR = __shfl_down_sync(FULL, s0, 1);
            int n0 = sL + s0 + s1;
            int n1 = s0 + s1 + s2;
            int n2 = s1 + s2 + s3;
            int n3 = s2 + s3 + sR;
            const int wr = v - 1;
            if (c.writeok && wr >= c.Y0 && wr < c.Y0 + TH && (unsigned)wr < (unsigned)HH) {
                float4 o = make_float4(n0 >= 8 ? 1.f : 0.f, n1 >= 8 ? 1.f : 0.f,
                                       n2 >= 8 ? 1.f : 0.f, n3 >= 8 ? 1.f : 0.f);
                float* op = c.dp + (size_t)wr * WW + c.c0;
                *reinterpret_cast<float4*>(op) = o;
                if (c.dup)
                    *reinterpret_cast<float4*>(op + NPIX) = o;   // mask == y
            }
        }
    }
}

template<bool FIN>
__global__ void __launch_bounds__(32) sweep_kernel(const float* __restrict__ src,
                                                   float* __restrict__ dst,
                                                   int dup)
{
    Ctx c;
    c.lane = threadIdx.x;
    const int sx = blockIdx.x;              // 0..8 column strips
    c.Y0 = blockIdx.y * TH;
    const int b = blockIdx.z;
    const int X0 = 120 * sx - 4;
    c.c0  = X0 + 4 * c.lane;
    c.ecc = (c.lane == 0) ? (c.c0 - 4) : (c.c0 + 4);
    c.sp  = src + (size_t)b * HH * WW;
    c.dp  = dst + (size_t)b * HH * WW;
    c.dup = dup;
    c.writeok = (c.lane >= 1) && (c.lane <= 30) && (c.c0 < WW);
    #pragma unroll
    for (int k = 0; k < 4; ++k) c.cv[k] = (unsigned)(c.c0 + k) < (unsigned)WW;
    c.CFIRST = FIN ? (c.Y0 - 2) : (c.Y0 - 1);
    const int rs = FIN ? (c.Y0 - 5) : (c.Y0 - 4);

    PK2(c.kC1, C1, C1);
    PK2(c.kC3, C3, C3);
    PK2(c.kM7, -C7, -C7);
    PK2(c.kM1, -1.0f, -1.0f);

    St s;
    #pragma unroll
    for (int i = 0; i < 7; ++i) { s.a[i][0] = 0ull; s.a[i][1] = 0ull; }
    #pragma unroll
    for (int k = 0; k < 4; ++k) {
        s.cp[k] = NEGINF; s.pm[k] = NEGINF; s.bp1[k] = 0; s.bp2[k] = 0;
    }
    s.ownN = ld4(c.sp, rs, c.c0);
    s.extN = (c.lane == 0 || c.lane == 31) ? ld4(c.sp, rs, c.ecc)
                                           : make_float4(0.f, 0.f, 0.f, 0.f);

    int r = rs;
    for (int it = 0; it < NOUT; ++it) {
        step<0, FIN>(s, c, r + 0);
        step<1, FIN>(s, c, r + 1);
        step<2, FIN>(s, c, r + 2);
        step<3, FIN>(s, c, r + 3);
        step<4, FIN>(s, c, r + 4);
        step<5, FIN>(s, c, r + 5);
        step<6, FIN>(s, c, r + 6);
        r += 7;
    }
}

extern "C" void kernel_launch(void* const* d_in, const int* in_sizes, int n_in,
                              void* d_out, int out_size)
{
    const float* x = (const float*)d_in[0];
    float* out = (float*)d_out;

    float *A, *B;
    cudaGetSymbolAddress((void**)&A, g_bufA);
    cudaGetSymbolAddress((void**)&B, g_bufB);

    dim3 grid(9, HH / TH, NB);   // (x-strips, row chunks, batch)
    dim3 block(32);

    int dup = (out_size >= 2 * NPIX) ? 1 : 0;

    sweep_kernel<false><<<grid, block>>>(x, A, 0);
    sweep_kernel<false><<<grid, block>>>(A, B, 0);
    sweep_kernel<false><<<grid, block>>>(B, A, 0);
    sweep_kernel<true ><<<grid, block>>>(A, out, dup);
}

// round 5
// speedup vs baseline: 2.1894x; 1.0263x over previous
#include <cuda_runtime.h>
#include <math_constants.h>

#define HH 1024
#define WW 1024
#define NB 16
#define NPIX (NB * HH * WW)
#define TH 32            // output rows per block (row chunk)
#define NOUT 6           // generic path: 6*7 = 42 steps

__device__ __align__(256) float g_bufA[NPIX];
__device__ __align__(256) float g_bufB[NPIX];

#define C1 (1.0f / 24.0f)
#define C3 (3.0f / 24.0f)
#define C7 (7.0f / 24.0f)
#define NEGINF (-CUDART_INF_F)

typedef unsigned long long u64;

// ---- packed f32x2 helpers ----
#define PK2(d, lo, hi)  asm("mov.b64 %0, {%1, %2};" : "=l"(d) : "f"(lo), "f"(hi))
#define UPK2(lo, hi, s) asm("mov.b64 {%0, %1}, %2;" : "=f"(lo), "=f"(hi) : "l"(s))
#define ADD2(d, a, b)   asm("add.rn.f32x2 %0, %1, %2;" : "=l"(d) : "l"(a), "l"(b))
#define ACC2(d, b)      asm("add.rn.f32x2 %0, %0, %1;" : "+l"(d) : "l"(b))
#define MUL2(d, a, b)   asm("mul.rn.f32x2 %0, %1, %2;" : "=l"(d) : "l"(a), "l"(b))
#define FMA2(d, a, b, c) asm("fma.rn.f32x2 %0, %1, %2, %3;" : "=l"(d) : "l"(a), "l"(b), "l"(c))

struct Ctx {
    const float* sp;
    float* dp;
    int lane, c0, ecc, Y0, CFIRST, dup;
    bool writeok, isEdge;
    bool cv[4];
    u64 kC1, kC3, kM7, kM1;
};

struct St {
    u64 a[7][2];
    float4 ownN, extN;
    float cp[4], pm[4];
    int bp1[4], bp2[4];
};

__device__ __forceinline__ float4 ld4(const float* __restrict__ p, int r, int cc) {
    if ((unsigned)r < (unsigned)HH && (unsigned)cc < (unsigned)WW)
        return *reinterpret_cast<const float4*>(p + (size_t)r * WW + cc);
    return make_float4(0.f, 0.f, 0.f, 0.f);
}

// ---- shared core: window build + packed filter + ring accumulate ----
template<int U>
__device__ __forceinline__ void core(St& s, const Ctx& c, float4 own, float4 ext,
                                     float raw[4])
{
    const unsigned FULL = 0xffffffffu;
    float w0 = __shfl_up_sync(FULL, own.y, 1);
    float w1 = __shfl_up_sync(FULL, own.z, 1);
    float w2 = __shfl_up_sync(FULL, own.w, 1);
    if (c.lane == 0) { w0 = ext.y; w1 = ext.z; w2 = ext.w; }
    float w7 = __shfl_down_sync(FULL, own.x, 1);
    float w8 = __shfl_down_sync(FULL, own.y, 1);
    float w9 = __shfl_down_sync(FULL, own.z, 1);
    if (c.lane == 31) { w7 = ext.x; w8 = ext.y; w9 = ext.z; }

    float w[10] = { w0, w1, w2, own.x, own.y, own.z, own.w, w7, w8, w9 };

    u64 P[9];
    #pragma unroll
    for (int j = 0; j < 9; ++j) PK2(P[j], w[j], w[j + 1]);

    #pragma unroll
    for (int p = 0; p < 2; ++p) {
        const int o = 2 * p;
        u64 t1, Pt, Puu, Pvv, Px2;
        ADD2(t1, P[2 + o], P[3 + o]);
        ADD2(Pt, t1, P[4 + o]);
        ADD2(Puu, P[1 + o], P[5 + o]);
        ADD2(Pvv, P[0 + o], P[6 + o]);
        ADD2(Px2, P[2 + o], P[4 + o]);

        u64 hA, hB, hC, hD, m1, m2, m3, i1, i2, i3;
        MUL2(hA, c.kC1, Pt);
        MUL2(m1, c.kC1, Puu);
        FMA2(hB, c.kC3, Pt, m1);
        MUL2(m2, c.kC1, P[0 + o]);
        FMA2(i1, c.kM7, P[3 + o], m2);
        FMA2(hC, c.kC3, Puu, i1);
        MUL2(m3, c.kC1, Pvv);
        FMA2(i2, c.kM7, Px2, m3);
        FMA2(i3, c.kC3, Puu, i2);
        FMA2(hD, c.kM1, P[3 + o], i3);

        ACC2(s.a[(U + 0) % 7][p], hA);
        ACC2(s.a[(U + 1) % 7][p], hB);
        ACC2(s.a[(U + 2) % 7][p], hC);
        ACC2(s.a[(U + 3) % 7][p], hD);
        ACC2(s.a[(U + 4) % 7][p], hC);
        ACC2(s.a[(U + 5) % 7][p], hB);
        ACC2(s.a[(U + 6) % 7][p], hA);
    }

    UPK2(raw[0], raw[1], s.a[U % 7][0]);
    UPK2(raw[2], raw[3], s.a[U % 7][1]);
    s.a[U % 7][0] = 0ull;
    s.a[U % 7][1] = 0ull;
}

// ================= SAFE path (no bounds checks anywhere) =================
template<int U, bool FIN, bool VM, bool WR>
__device__ __forceinline__ void step_safe(St& s, const Ctx& c,
                                          const float*& p0, const float*& pe,
                                          float*& wp)
{
    const unsigned FULL = 0xffffffffu;
    float4 own = s.ownN, ext = s.extN;
    s.ownN = *reinterpret_cast<const float4*>(p0);
    if (c.isEdge) s.extN = *reinterpret_cast<const float4*>(pe);
    p0 += WW; pe += WW;

    float raw[4];
    core<U>(s, c, own, ext, raw);

    if (VM) {
        float vm[4];
        #pragma unroll
        for (int k = 0; k < 4; ++k) {
            vm[k]  = fmaxf(s.pm[k], raw[k]);
            s.pm[k] = fmaxf(raw[k], s.cp[k]);
            s.cp[k] = raw[k];
        }
        float vmL = __shfl_up_sync(FULL, vm[3], 1);
        float vmR = __shfl_down_sync(FULL, vm[0], 1);
        float m0 = fmaxf(vmL,   fmaxf(vm[0], vm[1]));
        float m1 = fmaxf(vm[0], fmaxf(vm[1], vm[2]));
        float m2 = fmaxf(vm[1], fmaxf(vm[2], vm[3]));
        float m3 = fmaxf(vm[2], fmaxf(vm[3], vmR));

        if (!FIN) {
            if (WR && c.writeok)
                *reinterpret_cast<float4*>(wp) = make_float4(m0, m1, m2, m3);
        } else {
            int b0 = (m0 > 0.5f) ? 1 : 0;
            int b1 = (m1 > 0.5f) ? 1 : 0;
            int b2 = (m2 > 0.5f) ? 1 : 0;
            int b3 = (m3 > 0.5f) ? 1 : 0;
            int s0 = s.bp2[0] + s.bp1[0] + b0;
            int s1 = s.bp2[1] + s.bp1[1] + b1;
            int s2 = s.bp2[2] + s.bp1[2] + b2;
            int s3 = s.bp2[3] + s.bp1[3] + b3;
            s.bp2[0] = s.bp1[0]; s.bp2[1] = s.bp1[1];
            s.bp2[2] = s.bp1[2]; s.bp2[3] = s.bp1[3];
            s.bp1[0] = b0; s.bp1[1] = b1; s.bp1[2] = b2; s.bp1[3] = b3;
            int sL = __shfl_up_sync(FULL, s3, 1);
            int sR = __shfl_down_sync(FULL, s0, 1);
            if (WR && c.writeok) {
                float4 o = make_float4((sL + s0 + s1) >= 8 ? 1.f : 0.f,
                                       (s0 + s1 + s2) >= 8 ? 1.f : 0.f,
                                       (s1 + s2 + s3) >= 8 ? 1.f : 0.f,
                                       (s2 + s3 + sR) >= 8 ? 1.f : 0.f);
                *reinterpret_cast<float4*>(wp) = o;
                if (c.dup) *reinterpret_cast<float4*>(wp + NPIX) = o;
            }
        }
        wp += WW;
    }
}

template<bool FIN>
__device__ __forceinline__ void run_safe(const Ctx& c)
{
    St s;
    #pragma unroll
    for (int i = 0; i < 7; ++i) { s.a[i][0] = 0ull; s.a[i][1] = 0ull; }
    #pragma unroll
    for (int k = 0; k < 4; ++k) {
        s.cp[k] = NEGINF; s.pm[k] = NEGINF; s.bp1[k] = 0; s.bp2[k] = 0;
    }
    const int rs = FIN ? (c.Y0 - 5) : (c.Y0 - 4);
    s.ownN = *reinterpret_cast<const float4*>(c.sp + (size_t)rs * WW + c.c0);
    if (c.isEdge)
        s.extN = *reinterpret_cast<const float4*>(c.sp + (size_t)rs * WW + c.ecc);

    const float* p0 = c.sp + (size_t)(rs + 1) * WW + c.c0;
    const float* pe = c.sp + (size_t)(rs + 1) * WW + c.ecc;
    // wp initialized so it equals the first written row at the first WR step:
    // first VM step writes row (Y0-2) [non-FIN] / (Y0-4) [FIN] conceptually.
    float* wp = c.dp + (size_t)(FIN ? (c.Y0 - 4) : (c.Y0 - 2)) * WW + c.c0;

    #define SS(UU, VMf, WRf) step_safe<UU, FIN, VMf, WRf>(s, c, p0, pe, wp);

    if (!FIN) {
        SS(0,false,false) SS(1,false,false) SS(2,false,false)
        SS(3,false,false) SS(4,false,false) SS(5,false,false)
        SS(6,true,false)  SS(0,true,false)
        #pragma unroll 1
        for (int g = 0; g < 4; ++g) {
            SS(1,true,true) SS(2,true,true) SS(3,true,true) SS(4,true,true)
            SS(5,true,true) SS(6,true,true) SS(0,true,true)
        }
        SS(1,true,true) SS(2,true,true) SS(3,true,true) SS(4,true,true)
    } else {
        SS(0,false,false) SS(1,false,false) SS(2,false,false)
        SS(3,false,false) SS(4,false,false) SS(5,false,false)
        SS(6,true,false)  SS(0,true,false) SS(1,true,false) SS(2,true,false)
        #pragma unroll 1
        for (int g = 0; g < 4; ++g) {
            SS(3,true,true) SS(4,true,true) SS(5,true,true) SS(6,true,true)
            SS(0,true,true) SS(1,true,true) SS(2,true,true)
        }
        SS(3,true,true) SS(4,true,true) SS(5,true,true) SS(6,true,true)
    }
    #undef SS
}

// ================= GENERIC path (full runtime guards, R4 logic) =================
template<int U, bool FIN>
__device__ __forceinline__ void step_gen(St& s, const Ctx& c, int r)
{
    const unsigned FULL = 0xffffffffu;
    float4 own = s.ownN, ext = s.extN;
    s.ownN = ld4(c.sp, r + 1, c.c0);
    s.extN = c.isEdge ? ld4(c.sp, r + 1, c.ecc) : make_float4(0.f, 0.f, 0.f, 0.f);

    float raw[4];
    core<U>(s, c, own, ext, raw);

    const int cr = r - 3;
    if (cr >= c.CFIRST) {
        const bool rv = (unsigned)cr < (unsigned)HH;
        float cur[4], vm[4];
        #pragma unroll
        for (int k = 0; k < 4; ++k) {
            cur[k] = (rv && c.cv[k]) ? raw[k] : NEGINF;
            vm[k]  = fmaxf(s.pm[k], cur[k]);
            s.pm[k] = fmaxf(cur[k], s.cp[k]);
            s.cp[k] = cur[k];
        }
        float vmL = __shfl_up_sync(FULL, vm[3], 1);
        float vmR = __shfl_down_sync(FULL, vm[0], 1);
        float m0 = fmaxf(vmL,   fmaxf(vm[0], vm[1]));
        float m1 = fmaxf(vm[0], fmaxf(vm[1], vm[2]));
        float m2 = fmaxf(vm[1], fmaxf(vm[2], vm[3]));
        float m3 = fmaxf(vm[2], fmaxf(vm[3], vmR));
        const int v = cr - 1;

        if (!FIN) {
            if (c.writeok && v >= c.Y0 && v < c.Y0 + TH && v < HH)
                *reinterpret_cast<float4*>(c.dp + (size_t)v * WW + c.c0)
                    = make_float4(m0, m1, m2, m3);
        } else {
            const bool bv = (unsigned)v < (unsigned)HH;
            int b0 = (bv && c.cv[0] && m0 > 0.5f) ? 1 : 0;
            int b1 = (bv && c.cv[1] && m1 > 0.5f) ? 1 : 0;
            int b2 = (bv && c.cv[2] && m2 > 0.5f) ? 1 : 0;
            int b3 = (bv && c.cv[3] && m3 > 0.5f) ? 1 : 0;
            int s0 = s.bp2[0] + s.bp1[0] + b0;
            int s1 = s.bp2[1] + s.bp1[1] + b1;
            int s2 = s.bp2[2] + s.bp1[2] + b2;
            int s3 = s.bp2[3] + s.bp1[3] + b3;
            s.bp2[0] = s.bp1[0]; s.bp2[1] = s.bp1[1];
            s.bp2[2] = s.bp1[2]; s.bp2[3] = s.bp1[3];
            s.bp1[0] = b0; s.bp1[1] = b1; s.bp1[2] = b2; s.bp1[3] = b3;
            int sL = __shfl_up_sync(FULL, s3, 1);
            int sR = __shfl_down_sync(FULL, s0, 1);
            int n0 = sL + s0 + s1;
            int n1 = s0 + s1 + s2;
            int n2 = s1 + s2 + s3;
            int n3 = s2 + s3 + sR;
            const int wr = v - 1;
            if (c.writeok && wr >= c.Y0 && wr < c.Y0 + TH && (unsigned)wr < (unsigned)HH) {
                float4 o = make_float4(n0 >= 8 ? 1.f : 0.f, n1 >= 8 ? 1.f : 0.f,
                                       n2 >= 8 ? 1.f : 0.f, n3 >= 8 ? 1.f : 0.f);
                float* op = c.dp + (size_t)wr * WW + c.c0;
                *reinterpret_cast<float4*>(op) = o;
                if (c.dup) *reinterpret_cast<float4*>(op + NPIX) = o;
            }
        }
    }
}

template<bool FIN>
__device__ __forceinline__ void run_gen(const Ctx& c)
{
    St s;
    #pragma unroll
    for (int i = 0; i < 7; ++i) { s.a[i][0] = 0ull; s.a[i][1] = 0ull; }
    #pragma unroll
    for (int k = 0; k < 4; ++k) {
        s.cp[k] = NEGINF; s.pm[k] = NEGINF; s.bp1[k] = 0; s.bp2[k] = 0;
    }
    const int rs = FIN ? (c.Y0 - 5) : (c.Y0 - 4);
    s.ownN = ld4(c.sp, rs, c.c0);
    s.extN = c.isEdge ? ld4(c.sp, rs, c.ecc) : make_float4(0.f, 0.f, 0.f, 0.f);

    int r = rs;
    #pragma unroll 1
    for (int it = 0; it < NOUT; ++it) {
        step_gen<0, FIN>(s, c, r + 0);
        step_gen<1, FIN>(s, c, r + 1);
        step_gen<2, FIN>(s, c, r + 2);
        step_gen<3, FIN>(s, c, r + 3);
        step_gen<4, FIN>(s, c, r + 4);
        step_gen<5, FIN>(s, c, r + 5);
        step_gen<6, FIN>(s, c, r + 6);
        r += 7;
    }
}

template<bool FIN>
__global__ void __launch_bounds__(32) sweep_kernel(const float* __restrict__ src,
                                                   float* __restrict__ dst,
                                                   int dup)
{
    Ctx c;
    c.lane = threadIdx.x;
    const int sx = blockIdx.x;              // 0..8 column strips
    const int by = blockIdx.y;
    c.Y0 = by * TH;
    const int b = blockIdx.z;
    const int X0 = 120 * sx - 4;
    c.c0  = X0 + 4 * c.lane;
    c.ecc = (c.lane == 0) ? (c.c0 - 4) : (c.c0 + 4);
    c.sp  = src + (size_t)b * HH * WW;
    c.dp  = dst + (size_t)b * HH * WW;
    c.dup = dup;
    c.isEdge = (c.lane == 0) || (c.lane == 31);
    c.writeok = (c.lane >= 1) && (c.lane <= 30) && (c.c0 < WW);
    #pragma unroll
    for (int k = 0; k < 4; ++k) c.cv[k] = (unsigned)(c.c0 + k) < (unsigned)WW;
    c.CFIRST = FIN ? (c.Y0 - 2) : (c.Y0 - 1);

    PK2(c.kC1, C1, C1);
    PK2(c.kC3, C3, C3);
    PK2(c.kM7, -C7, -C7);
    PK2(c.kM1, -1.0f, -1.0f);

    const bool safe = (sx >= 1) && (sx <= 7) && (by >= 1) && (by <= 30);
    if (safe) run_safe<FIN>(c);
    else      run_gen<FIN>(c);
}

extern "C" void kernel_launch(void* const* d_in, const int* in_sizes, int n_in,
                              void* d_out, int out_size)
{
    const float* x = (const float*)d_in[0];
    float* out = (float*)d_out;

    float *A, *B;
    cudaGetSymbolAddress((void**)&A, g_bufA);
    cudaGetSymbolAddress((void**)&B, g_bufB);

    dim3 grid(9, HH / TH, NB);
    dim3 block(32);

    int dup = (out_size >= 2 * NPIX) ? 1 : 0;

    sweep_kernel<false><<<grid, block>>>(x, A, 0);
    sweep_kernel<false><<<grid, block>>>(A, B, 0);
    sweep_kernel<false><<<grid, block>>>(B, A, 0);
    sweep_kernel<true ><<<grid, block>>>(A, out, dup);
}